// round 17
// baseline (speedup 1.0000x reference)
#include <cuda_runtime.h>
#include <cuda_fp16.h>
#include <stdint.h>

// Problem constants
#define T_TOK 2048
#define H_DIM 1024
#define I_DIM 768
#define E_NUM 8
#define K_TOP 2
#define A_TOT (T_TOK * K_TOP)   // 4096
#define MAXBLK 40               // A_TOT/128 + E_NUM
#define NT1 12                  // gemm1 column tiles per row block (I/64)
#define NT2 8                   // gemm2 column tiles per row block (H/128)
#define NWGU 192                // Wgu conversion chunks (8e x 24 blocks of 64 rows)
#define NWD  64                 // Wd conversion chunks (8e x 8 blocks of 128 rows)
#define NCONV (NWGU + NWD)      // 256

// ---------------------------------------------------------------------------
// Device-global scratch
// ---------------------------------------------------------------------------
__device__ int   g_count[E_NUM];
__device__ int   g_offset[E_NUM];
__device__ int   g_perm[A_TOT];
__device__ int   g_nblk;
__device__ int   g_be[MAXBLK];
__device__ int   g_bm[MAXBLK];
__device__ int   g_ticket;
__device__ int   g_flag[MAXBLK];          // gemm1 tiles done per row block
__device__ int   g_wguflag[E_NUM * NT1];  // 96: (e,nt) -> 2 when both chunks done
__device__ int   g_wdflag[E_NUM * NT2];   // 64: (e,j) -> 1 when chunk done
__device__ __half g_x  [(size_t)T_TOK * H_DIM];
__device__ __half g_wgu[(size_t)E_NUM * 2 * I_DIM * H_DIM];
__device__ __half g_wd [(size_t)E_NUM * H_DIM * I_DIM];
__device__ __half g_act[(size_t)A_TOT * I_DIM];

// ---------------------------------------------------------------------------
// PTX helpers
// ---------------------------------------------------------------------------
__device__ __forceinline__ uint32_t smem_u32(const void* p) {
    uint32_t a;
    asm("{ .reg .u64 t; cvta.to.shared.u64 t, %1; cvt.u32.u64 %0, t; }" : "=r"(a) : "l"(p));
    return a;
}

#define LDSM_X4(R0, R1, R2, R3, ADDR) \
    asm volatile("ldmatrix.sync.aligned.m8n8.x4.shared.b16 {%0,%1,%2,%3}, [%4];" \
        : "=r"(R0), "=r"(R1), "=r"(R2), "=r"(R3) : "r"(ADDR))

#define MMA_F16(D, A, B0, B1) \
    asm volatile("mma.sync.aligned.m16n8k16.row.col.f32.f16.f16.f32 " \
        "{%0,%1,%2,%3}, {%4,%5,%6,%7}, {%8,%9}, {%0,%1,%2,%3};" \
        : "+f"((D)[0]), "+f"((D)[1]), "+f"((D)[2]), "+f"((D)[3]) \
        : "r"((A)[0]), "r"((A)[1]), "r"((A)[2]), "r"((A)[3]), "r"(B0), "r"(B1))

#define CP_ASYNC16(DST, SRC, SZ) \
    asm volatile("cp.async.cg.shared.global [%0], [%1], 16, %2;" \
        :: "r"(DST), "l"(SRC), "r"(SZ))
#define CP_COMMIT  asm volatile("cp.async.commit_group;" ::: "memory")
#define CP_WAIT1   asm volatile("cp.async.wait_group 1;" ::: "memory")
#define CP_WAIT0   asm volatile("cp.async.wait_group 0;" ::: "memory")

__device__ __forceinline__ uint32_t pack_h2(__half a, __half b) {
    return (uint32_t)__half_as_ushort(a) | ((uint32_t)__half_as_ushort(b) << 16);
}

// ---------------------------------------------------------------------------
// prep: X conversion + output zero (blocks 0..255) and routing + flag reset
// (block 256).  65536 conv threads: X 524288 float4 -> 8 iters; zero -> 8.
// ---------------------------------------------------------------------------
__global__ void prep_all(const float* __restrict__ X,
                         const int* __restrict__ topk,
                         float* __restrict__ out) {
    __shared__ int cnt[E_NUM], cur[E_NUM];
    const int tid = threadIdx.x;

    if (blockIdx.x == 256) {
        if (tid < E_NUM) cnt[tid] = 0;
        for (int i = tid; i < E_NUM * NT1; i += 256) g_wguflag[i] = 0;
        for (int i = tid; i < E_NUM * NT2; i += 256) g_wdflag[i] = 0;
        for (int i = tid; i < MAXBLK; i += 256) g_flag[i] = 0;
        if (tid == 0) g_ticket = 0;
        __syncthreads();
        for (int a = tid; a < A_TOT; a += 256) atomicAdd(&cnt[topk[a]], 1);
        __syncthreads();
        if (tid == 0) {
            int s = 0, idx = 0;
            for (int e = 0; e < E_NUM; e++) {
                g_count[e] = cnt[e];
                g_offset[e] = s;
                cur[e] = s;
                s += cnt[e];
                for (int mb = 0; mb * 128 < cnt[e]; mb++) {
                    g_be[idx] = e;
                    g_bm[idx] = mb * 128;
                    idx++;
                }
            }
            g_nblk = idx;
        }
        __syncthreads();
        for (int a = tid; a < A_TOT; a += 256) {
            int e = topk[a];
            int s = atomicAdd(&cur[e], 1);
            g_perm[s] = a;
        }
        return;
    }

    const int t = blockIdx.x * 256 + tid;   // 0..65535
    #pragma unroll
    for (int j = 0; j < 8; j++) {
        int i = t + j * 65536;
        float4 v = ((const float4*)X)[i];
        uint2 u;
        u.x = pack_h2(__float2half_rn(v.x), __float2half_rn(v.y));
        u.y = pack_h2(__float2half_rn(v.z), __float2half_rn(v.w));
        ((uint2*)g_x)[i] = u;
    }
    #pragma unroll
    for (int j = 0; j < 8; j++) {
        int i = t + j * 65536;
        ((float4*)out)[i] = make_float4(0.f, 0.f, 0.f, 0.f);
    }
}

// ---------------------------------------------------------------------------
// SMEM: KC=64 fp16 cols, stride 72, 2 stages.  72 KB/CTA, 2 CTAs/SM.
// ---------------------------------------------------------------------------
#define KC       64
#define STRIDE   72
#define TILE_E   (128 * STRIDE)       // 9216 elems
#define STAGE_E  (2 * TILE_E)         // 18432
#define SMEM_BYTES (2 * STAGE_E * 2)  // 73728 B

__device__ __forceinline__ void load_afrag(uint32_t sb, int eoff, int row0, int kk,
                                           int lane, uint32_t a[4]) {
    int row = row0 + (lane & 15);
    int col = kk + ((lane >> 4) << 3);
    uint32_t addr = sb + (uint32_t)(eoff + row * STRIDE + col) * 2;
    LDSM_X4(a[0], a[1], a[2], a[3], addr);
}
__device__ __forceinline__ void load_bfrag(uint32_t sb, int eoff, int nbase, int kk,
                                           int lane, uint32_t b[4]) {
    int row = nbase + (((lane >> 4) & 1) << 3) + (lane & 7);
    int col = kk + (((lane >> 3) & 1) << 3);
    uint32_t addr = sb + (uint32_t)(eoff + row * STRIDE + col) * 2;
    LDSM_X4(b[0], b[1], b[2], b[3], addr);
}

#define NCH1 (H_DIM / KC)   // 16
#define NCH2 (I_DIM / KC)   // 12

// ---------------------------------------------------------------------------
// Conversion item bodies (run inside the persistent kernel)
// ---------------------------------------------------------------------------
// Wgu chunk c in [0,192): e = c/24, b = c%24 -> rows [e*1536 + b*64, +64)
__device__ void conv_wgu_item(int c, const float* __restrict__ Wgu) {
    const int tid = threadIdx.x;
    const int e = c / 24, b = c % 24;
    const int off4 = (e * 1536 + b * 64) * (H_DIM / 4);   // float4 index
    #pragma unroll
    for (int j = 0; j < 64; j++) {
        int i = off4 + tid + j * 256;
        float4 v = ((const float4*)Wgu)[i];
        uint2 u;
        u.x = pack_h2(__float2half_rn(v.x), __float2half_rn(v.y));
        u.y = pack_h2(__float2half_rn(v.z), __float2half_rn(v.w));
        ((uint2*)g_wgu)[i] = u;
    }
    __threadfence();
    __syncthreads();
    if (tid == 0) {
        int nt = (b < NT1) ? b : b - NT1;
        atomicAdd(&g_wguflag[e * NT1 + nt], 1);
    }
}

// Wd chunk c in [0,64): e = c/8, j = c%8 -> rows [e*1024 + j*128, +128)
__device__ void conv_wd_item(int c, const float* __restrict__ Wd) {
    const int tid = threadIdx.x;
    const int e = c / NT2, jb = c % NT2;
    const int off4 = (e * H_DIM + jb * 128) * (I_DIM / 4);
    #pragma unroll
    for (int j = 0; j < 96; j++) {
        int i = off4 + tid + j * 256;
        float4 v = ((const float4*)Wd)[i];
        uint2 u;
        u.x = pack_h2(__float2half_rn(v.x), __float2half_rn(v.y));
        u.y = pack_h2(__float2half_rn(v.z), __float2half_rn(v.w));
        ((uint2*)g_wd)[i] = u;
    }
    __threadfence();
    __syncthreads();
    if (tid == 0) atomicAdd(&g_wdflag[c], 1);
}

// ---------------------------------------------------------------------------
// GEMM1 body: waits for its Wgu chunks, computes, bumps g_flag[bx].
// ---------------------------------------------------------------------------
__device__ void gemm1_body(int bx, int nt, char* smem_raw) {
    const int e    = g_be[bx];
    const int m0   = g_bm[bx];
    const int n0g  = nt * 64;
    const int cnt  = g_count[e];
    const int off  = g_offset[e];
    const int cntm = cnt - m0;

    const int tid = threadIdx.x, lane = tid & 31, wid = tid >> 5;
    const int wm = wid & 3, wn = wid >> 2;

    // wait for this tile's weight chunks (gate + up)
    if (tid == 0) {
        volatile int* f = &g_wguflag[e * NT1 + nt];
        while (*f < 2) { }
    }
    __syncthreads();
    __threadfence();

    __half* smem = (__half*)smem_raw;
    __shared__ int rowtok[128];
    const uint32_t sb = smem_u32(smem);

    if (tid < 128)
        rowtok[tid] = (tid < cntm) ? g_perm[off + m0 + tid] / K_TOP : -1;
    __syncthreads();

    const __half* wb = g_wgu + (size_t)e * (2 * I_DIM) * H_DIM;

    auto issue = [&](int k0, int soE) {
        #pragma unroll
        for (int i = 0; i < 8; i++) {
            int idx = tid + i * 256;
            int mat = idx >> 10;             // 0=A 1=B
            int row = (idx >> 3) & 127;
            int seg = idx & 7;
            uint32_t dst = sb + (uint32_t)(soE + mat * TILE_E + row * STRIDE + seg * 8) * 2;
            if (mat == 0) {
                int tok = rowtok[row];
                const __half* src = g_x + (size_t)(tok < 0 ? 0 : tok) * H_DIM + k0 + seg * 8;
                CP_ASYNC16(dst, src, (tok < 0) ? 0u : 16u);
            } else {
                int wr = (row < 64) ? (n0g + row) : (I_DIM + n0g + row - 64);
                const __half* src = wb + (size_t)wr * H_DIM + k0 + seg * 8;
                CP_ASYNC16(dst, src, 16u);
            }
        }
        CP_COMMIT;
    };

    float accG[2][4][4], accU[2][4][4];
    #pragma unroll
    for (int a = 0; a < 2; a++)
        #pragma unroll
        for (int b = 0; b < 4; b++)
            #pragma unroll
            for (int c = 0; c < 4; c++) { accG[a][b][c] = 0.f; accU[a][b][c] = 0.f; }

    issue(0, 0);

    for (int c = 0; c < NCH1; c++) {
        const int s = c & 1;
        if (c + 1 < NCH1) { issue((c + 1) * KC, (s ^ 1) * STAGE_E); CP_WAIT1; }
        else CP_WAIT0;
        __syncthreads();

        const int so = s * STAGE_E;
        #pragma unroll
        for (int kk = 0; kk < KC; kk += 16) {
            uint32_t ah[2][4], bg[2][4], bu[2][4];
            #pragma unroll
            for (int mt = 0; mt < 2; mt++)
                load_afrag(sb, so, wm * 32 + mt * 16, kk, lane, ah[mt]);
            #pragma unroll
            for (int p = 0; p < 2; p++) {
                load_bfrag(sb, so + TILE_E, wn * 32 + p * 16,      kk, lane, bg[p]);
                load_bfrag(sb, so + TILE_E, wn * 32 + p * 16 + 64, kk, lane, bu[p]);
            }
            #pragma unroll
            for (int p = 0; p < 2; p++) {
                #pragma unroll
                for (int mt = 0; mt < 2; mt++) {
                    #pragma unroll
                    for (int q = 0; q < 2; q++) {
                        MMA_F16(accG[mt][2 * p + q], ah[mt], bg[p][2 * q], bg[p][2 * q + 1]);
                        MMA_F16(accU[mt][2 * p + q], ah[mt], bu[p][2 * q], bu[p][2 * q + 1]);
                    }
                }
            }
        }
        __syncthreads();
    }

    // epilogue: silu(gate)*up -> fp16 act
    const int gid = lane >> 2, tig = lane & 3;
    #pragma unroll
    for (int mt = 0; mt < 2; mt++) {
        #pragma unroll
        for (int nt2 = 0; nt2 < 4; nt2++) {
            int colg = n0g + wn * 32 + nt2 * 8 + 2 * tig;
            #pragma unroll
            for (int h = 0; h < 2; h++) {
                int rowl = wm * 32 + mt * 16 + gid + h * 8;
                if (rowl < cntm) {
                    float g0 = accG[mt][nt2][2 * h],     u0 = accU[mt][nt2][2 * h];
                    float g1 = accG[mt][nt2][2 * h + 1], u1 = accU[mt][nt2][2 * h + 1];
                    float v0 = (g0 / (1.f + __expf(-g0))) * u0;
                    float v1 = (g1 / (1.f + __expf(-g1))) * u1;
                    size_t o = (size_t)(off + m0 + rowl) * I_DIM + colg;
                    *(uint32_t*)(g_act + o) = pack_h2(__float2half_rn(v0), __float2half_rn(v1));
                }
            }
        }
    }

    __threadfence();
    __syncthreads();
    if (tid == 0) atomicAdd(&g_flag[bx], 1);
}

// ---------------------------------------------------------------------------
// GEMM2 body (+ fused combine): waits for gemm1 row block + its Wd chunk.
// ---------------------------------------------------------------------------
__device__ void gemm2_body(int bx, int jn, const float* __restrict__ wts,
                           float* __restrict__ out, char* smem_raw) {
    const int tid = threadIdx.x, lane = tid & 31, wid = tid >> 5;
    const int e    = g_be[bx];
    const int m0   = g_bm[bx];
    const int n0   = jn * 128;

    if (tid == 0) {
        volatile int* f1 = &g_flag[bx];
        volatile int* f2 = &g_wdflag[e * NT2 + jn];
        while (*f1 < NT1 || *f2 < 1) { }
    }
    __syncthreads();
    __threadfence();

    const int cnt  = g_count[e];
    const int off  = g_offset[e];
    const int cntm = cnt - m0;

    __half* smem = (__half*)smem_raw;
    const uint32_t sb = smem_u32(smem);
    const int wm = wid & 3, wn = wid >> 2;

    const __half* wb = g_wd + (size_t)e * H_DIM * I_DIM;

    auto issue = [&](int k0, int soE) {
        #pragma unroll
        for (int i = 0; i < 8; i++) {
            int idx = tid + i * 256;
            int mat = idx >> 10;
            int row = (idx >> 3) & 127;
            int seg = idx & 7;
            uint32_t dst = sb + (uint32_t)(soE + mat * TILE_E + row * STRIDE + seg * 8) * 2;
            if (mat == 0) {
                int r = (row < cntm) ? row : 0;
                const __half* src = g_act + (size_t)(off + m0 + r) * I_DIM + k0 + seg * 8;
                CP_ASYNC16(dst, src, (row < cntm) ? 16u : 0u);
            } else {
                const __half* src = wb + (size_t)(n0 + row) * I_DIM + k0 + seg * 8;
                CP_ASYNC16(dst, src, 16u);
            }
        }
        CP_COMMIT;
    };

    float acc[2][8][4];
    #pragma unroll
    for (int a = 0; a < 2; a++)
        #pragma unroll
        for (int b = 0; b < 8; b++)
            #pragma unroll
            for (int c = 0; c < 4; c++) acc[a][b][c] = 0.f;

    issue(0, 0);

    for (int c = 0; c < NCH2; c++) {
        const int s = c & 1;
        if (c + 1 < NCH2) { issue((c + 1) * KC, (s ^ 1) * STAGE_E); CP_WAIT1; }
        else CP_WAIT0;
        __syncthreads();

        const int so = s * STAGE_E;
        #pragma unroll
        for (int kk = 0; kk < KC; kk += 16) {
            uint32_t ah[2][4], bh[4][4];
            #pragma unroll
            for (int mt = 0; mt < 2; mt++)
                load_afrag(sb, so, wm * 32 + mt * 16, kk, lane, ah[mt]);
            #pragma unroll
            for (int p = 0; p < 4; p++)
                load_bfrag(sb, so + TILE_E, wn * 64 + p * 16, kk, lane, bh[p]);
            #pragma unroll
            for (int p = 0; p < 4; p++) {
                #pragma unroll
                for (int mt = 0; mt < 2; mt++) {
                    #pragma unroll
                    for (int q = 0; q < 2; q++)
                        MMA_F16(acc[mt][2 * p + q], ah[mt], bh[p][2 * q], bh[p][2 * q + 1]);
                }
            }
        }
        __syncthreads();
    }

    const int gid = lane >> 2, tig = lane & 3;
    #pragma unroll
    for (int mt = 0; mt < 2; mt++) {
        #pragma unroll
        for (int h = 0; h < 2; h++) {
            int rowl = wm * 32 + mt * 16 + gid + h * 8;
            if (rowl < cntm) {
                int a = g_perm[off + m0 + rowl];
                int t = a / K_TOP;
                float w = wts[a];
                float* obase = out + (size_t)t * H_DIM;
                #pragma unroll
                for (int nt = 0; nt < 8; nt++) {
                    int col = n0 + wn * 64 + nt * 8 + 2 * tig;
                    float2 r = make_float2(w * acc[mt][nt][2 * h],
                                           w * acc[mt][nt][2 * h + 1]);
                    atomicAdd((float2*)(obase + col), r);
                }
            }
        }
    }
}

// ---------------------------------------------------------------------------
// Persistent kernel: tickets = [conv_wgu 192][conv_wd 64][gemm1 12*nb][gemm2 8*nb]
// ---------------------------------------------------------------------------
__global__ __launch_bounds__(256, 2)
void moe_gemms(const float* __restrict__ Wgu, const float* __restrict__ Wd,
               const float* __restrict__ wts, float* __restrict__ out) {
    extern __shared__ char smem_raw[];
    __shared__ int s_id;
    if (threadIdx.x == 0) s_id = atomicAdd(&g_ticket, 1);
    __syncthreads();
    const int id = s_id;

    if (id < NWGU) { conv_wgu_item(id, Wgu); return; }
    if (id < NCONV) { conv_wd_item(id - NWGU, Wd); return; }

    const int nb = g_nblk;
    int j = id - NCONV;
    if (j < nb * NT1) {
        gemm1_body(j / NT1, j % NT1, smem_raw);
        return;
    }
    j -= nb * NT1;
    if (j < nb * NT2) {
        gemm2_body(j / NT2, j % NT2, wts, out, smem_raw);
    }
}

// ---------------------------------------------------------------------------
// Launch
// ---------------------------------------------------------------------------
extern "C" void kernel_launch(void* const* d_in, const int* in_sizes, int n_in,
                              void* d_out, int out_size) {
    const float* X    = (const float*)d_in[0];
    const float* Wgu  = (const float*)d_in[1];
    const float* Wd   = (const float*)d_in[2];
    const int*   topk = (const int*)  d_in[3];
    const float* wts  = (const float*)d_in[4];
    float*       out  = (float*)d_out;

    cudaFuncSetAttribute(moe_gemms, cudaFuncAttributeMaxDynamicSharedMemorySize, SMEM_BYTES);

    prep_all<<<257, 256>>>(X, topk, out);
    moe_gemms<<<NCONV + MAXBLK * (NT1 + NT2), 256, SMEM_BYTES>>>(Wgu, Wd, wts, out);
}